// round 15
// baseline (speedup 1.0000x reference)
#include <cuda_runtime.h>
#include <cuda_fp16.h>
#include <math.h>
#include <cstdint>

#define BATCH 4
#define NSEQ 1024
#define DIM 1024
#define HEADS 16
#define DHEAD 64
#define INNER 1024
#define SCALE 0.125f

typedef __half f16;
typedef __half2 f162;

// ---------------- scratch (device globals; allocation-free) ----------------
#define NELEM_X   ((long long)BATCH * NSEQ * DIM)
#define NELEM_WQ  ((long long)DIM * INNER)
#define NELEM_WKV ((long long)DIM * 2 * INNER)
#define NELEM_WO  ((long long)INNER * DIM)
#define NELEM_Q   ((long long)BATCH * NSEQ * INNER)
#define NELEM_KV  ((long long)BATCH * NSEQ * 2 * INNER)
#define NELEM_ATT ((long long)BATCH * HEADS * NSEQ * NSEQ)

__device__ f16 g_xh[NELEM_X],   g_xl[NELEM_X];
__device__ f16 g_wqh[NELEM_WQ], g_wql[NELEM_WQ];
__device__ f16 g_wkvh[NELEM_WKV], g_wkvl[NELEM_WKV];
__device__ f16 g_woh[NELEM_WO], g_wol[NELEM_WO];
__device__ f16 g_qh[NELEM_Q],   g_ql[NELEM_Q];
__device__ f16 g_kvh[NELEM_KV], g_kvl[NELEM_KV];
__device__ f16 g_dots[NELEM_ATT];       // fp16 now: 128 MB
__device__ f16 g_ah[NELEM_ATT];         // attn hi only
__device__ f16 g_mh[NELEM_Q];           // mid hi only

__device__ __forceinline__ void split_f16(float x, f16& h, f16& l) {
    h = __float2half(x);
    l = __float2half(x - __half2float(h));
}
__device__ __forceinline__ void cp16(uint32_t s, const void* g) {
    asm volatile("cp.async.cg.shared.global [%0], [%1], 16;" :: "r"(s), "l"(g));
}
__device__ __forceinline__ void cp_commit() { asm volatile("cp.async.commit_group;"); }
template<int N>
__device__ __forceinline__ void cp_wait() { asm volatile("cp.async.wait_group %0;" :: "n"(N)); }

__device__ __forceinline__ void ldsm4(uint32_t* r, uint32_t a) {
    asm volatile("ldmatrix.sync.aligned.m8n8.x4.shared.b16 {%0,%1,%2,%3}, [%4];"
                 : "=r"(r[0]), "=r"(r[1]), "=r"(r[2]), "=r"(r[3]) : "r"(a));
}
__device__ __forceinline__ void ldsm4t(uint32_t* r, uint32_t a) {
    asm volatile("ldmatrix.sync.aligned.m8n8.x4.trans.shared.b16 {%0,%1,%2,%3}, [%4];"
                 : "=r"(r[0]), "=r"(r[1]), "=r"(r[2]), "=r"(r[3]) : "r"(a));
}
__device__ __forceinline__ void mma16816(float* c, const uint32_t* a, const uint32_t* b) {
    asm volatile("mma.sync.aligned.m16n8k16.row.col.f32.f16.f16.f32 "
                 "{%0,%1,%2,%3}, {%4,%5,%6,%7}, {%8,%9}, {%0,%1,%2,%3};"
                 : "+f"(c[0]), "+f"(c[1]), "+f"(c[2]), "+f"(c[3])
                 : "r"(a[0]), "r"(a[1]), "r"(a[2]), "r"(a[3]), "r"(b[0]), "r"(b[1]));
}
__device__ __forceinline__ void stcs32(f16* p, uint32_t v) {
    asm volatile("st.global.cs.b32 [%0], %1;" :: "l"(p), "r"(v) : "memory");
}
__device__ __forceinline__ uint32_t ldcs32(const f16* p) {
    uint32_t v;
    asm volatile("ld.global.cs.b32 %0, [%1];" : "=r"(v) : "l"(p));
    return v;
}

// ---------------- fused split: all four f32 inputs -> f16 hi/lo -------------
#define X4   (NELEM_X / 4)
#define WQ4  (NELEM_WQ / 4)
#define WKV4 (NELEM_WKV / 4)
#define WO4  (NELEM_WO / 4)
#define TOT4 (X4 + WQ4 + WKV4 + WO4)

__global__ void split_all(const float* __restrict__ x, f16* __restrict__ xh, f16* __restrict__ xl,
                          const float* __restrict__ wq, f16* __restrict__ wqh, f16* __restrict__ wql,
                          const float* __restrict__ wkv, f16* __restrict__ wkvh, f16* __restrict__ wkvl,
                          const float* __restrict__ wo, f16* __restrict__ woh, f16* __restrict__ wol) {
    long long i = (long long)blockIdx.x * blockDim.x + threadIdx.x;
    if (i >= TOT4) return;
    const float* in; f16 *hi, *lo; long long o;
    if (i < X4)                    { in = x;   hi = xh;   lo = xl;   o = i; }
    else if (i < X4 + WQ4)         { in = wq;  hi = wqh;  lo = wql;  o = i - X4; }
    else if (i < X4 + WQ4 + WKV4)  { in = wkv; hi = wkvh; lo = wkvl; o = i - X4 - WQ4; }
    else                           { in = wo;  hi = woh;  lo = wol;  o = i - X4 - WQ4 - WKV4; }
    float4 v = reinterpret_cast<const float4*>(in)[o];
    f16 h0, l0, h1, l1, h2, l2, h3, l3;
    split_f16(v.x, h0, l0); split_f16(v.y, h1, l1);
    split_f16(v.z, h2, l2); split_f16(v.w, h3, l3);
    reinterpret_cast<f162*>(hi)[o * 2]     = __halves2half2(h0, h1);
    reinterpret_cast<f162*>(hi)[o * 2 + 1] = __halves2half2(h2, h3);
    reinterpret_cast<f162*>(lo)[o * 2]     = __halves2half2(l0, l1);
    reinterpret_cast<f162*>(lo)[o * 2 + 1] = __halves2half2(l2, l3);
}

// ---------------------------------------------------------------------------
// Raw mma.sync fp16 split GEMM, 2-buffer cp.async pipeline, OCC CTAs/SM.
//   TERMS=3: acc = Ah(Bh+Bl) + Al·Bh.   TERMS=2: acc = Ah(Bh+Bl).
//   OUT: 0 f32 direct, 1 f32+bias smem, 2 split f16 hi/lo smem,
//        3 f16 hi smem, 4 f16 direct streaming (st.global.cs).
// ---------------------------------------------------------------------------
template<int BN, int NWARP, bool BTRANS, int TERMS, int OUT, int OCC>
__global__ void __launch_bounds__(NWARP * 32, OCC)
mma_gemm(const f16* __restrict__ Ah, const f16* __restrict__ Al,
         const f16* __restrict__ Bh, const f16* __restrict__ Bl,
         float* __restrict__ Cf, f16* __restrict__ Ch, f16* __restrict__ Cl,
         const float* __restrict__ bias,
         int K, int lda, int ldb, int ldc,
         long long sa_b, long long sa_h,
         long long sb_b, long long sb_h,
         long long sc_b, long long sc_h,
         float out_scale)
{
    constexpr int NT = NWARP * 32;
    constexpr int WARPS_N = BN / 32;
    constexpr int LDA_S = 40;
    constexpr int LDBT = BN + 8;
    constexpr int SA_E = 128 * LDA_S;
    constexpr int SB_E = BTRANS ? 32 * LDBT : BN * LDA_S;
    constexpr int NAH = (TERMS == 3) ? 2 : 1;
    constexpr int BNP = BN + 4;

    extern __shared__ char smem[];
    const uint32_t aAh = (uint32_t)__cvta_generic_to_shared(smem);
    const uint32_t aAl = aAh + 2 * SA_E * 2;
    const uint32_t aBh = aAh + 2 * SA_E * 2 * NAH;
    const uint32_t aBl = aBh + 2 * SB_E * 2;
    float* sE = reinterpret_cast<float*>(smem);

    const int tid = threadIdx.x;
    const int warp = tid >> 5, lane = tid & 31;
    const int wm = (warp / WARPS_N) * 64;
    const int wn = (warp % WARPS_N) * 32;

    const int z = blockIdx.z, zb = z >> 4, zh = z & 15;
    Ah += zb * sa_b + zh * sa_h;
    if (TERMS == 3) Al += zb * sa_b + zh * sa_h;
    Bh += zb * sb_b + zh * sb_h;  Bl += zb * sb_b + zh * sb_h;
    if (OUT >= 2) { Ch += zb * sc_b + zh * sc_h; if (OUT == 2) Cl += zb * sc_b + zh * sc_h; }
    else          { Cf += zb * sc_b + zh * sc_h; }

    const int bm = blockIdx.y * 128, bn = blockIdx.x * BN;

    float acc[4][4][4] = {};

    auto load_stage = [&](int s) {
        const int buf = s & 1;
        const int k0 = s * 32;
        const uint32_t bA = (uint32_t)buf * SA_E * 2;
        const uint32_t bB = (uint32_t)buf * SB_E * 2;
        #pragma unroll
        for (int c = tid; c < 512; c += NT) {
            int r = c >> 2, ck = (c & 3) * 8;
            long long g = (long long)(bm + r) * lda + k0 + ck;
            uint32_t so = bA + (uint32_t)(r * LDA_S + ck) * 2;
            cp16(aAh + so, Ah + g);
            if (TERMS == 3) cp16(aAl + so, Al + g);
        }
        if (BTRANS) {
            #pragma unroll
            for (int c = tid; c < 32 * (BN / 8); c += NT) {
                int kr = c / (BN / 8), nc = (c % (BN / 8)) * 8;
                long long g = (long long)(k0 + kr) * ldb + bn + nc;
                uint32_t so = bB + (uint32_t)(kr * LDBT + nc) * 2;
                cp16(aBh + so, Bh + g);
                cp16(aBl + so, Bl + g);
            }
        } else {
            #pragma unroll
            for (int c = tid; c < BN * 4; c += NT) {
                int r = c >> 2, ck = (c & 3) * 8;
                long long g = (long long)(bn + r) * ldb + k0 + ck;
                uint32_t so = bB + (uint32_t)(r * LDA_S + ck) * 2;
                cp16(aBh + so, Bh + g);
                cp16(aBl + so, Bl + g);
            }
        }
        cp_commit();
    };

    const int S = K / 32;
    load_stage(0);

    for (int s = 0; s < S; s++) {
        cp_wait<0>();
        __syncthreads();
        if (s + 1 < S) load_stage(s + 1);

        const int buf = s & 1;
        const uint32_t bA = (uint32_t)buf * SA_E * 2;
        const uint32_t bB = (uint32_t)buf * SB_E * 2;

        #pragma unroll
        for (int kk = 0; kk < 32; kk += 16) {
            uint32_t a_h[4][4], a_l[4][4];
            #pragma unroll
            for (int mi = 0; mi < 4; mi++) {
                uint32_t ao = bA + (uint32_t)((wm + mi * 16 + (lane & 15)) * LDA_S
                                              + kk + (lane >> 4) * 8) * 2;
                ldsm4(a_h[mi], aAh + ao);
                if (TERMS == 3) ldsm4(a_l[mi], aAl + ao);
            }
            uint32_t b_h[4][2], b_l[4][2];
            #pragma unroll
            for (int ni = 0; ni < 2; ni++) {
                uint32_t r4[4];
                if (BTRANS) {
                    uint32_t bo = bB + (uint32_t)((kk + (lane & 15)) * LDBT
                                                  + wn + ni * 16 + (lane >> 4) * 8) * 2;
                    ldsm4t(r4, aBh + bo);
                    b_h[2*ni][0] = r4[0]; b_h[2*ni][1] = r4[1];
                    b_h[2*ni+1][0] = r4[2]; b_h[2*ni+1][1] = r4[3];
                    ldsm4t(r4, aBl + bo);
                    b_l[2*ni][0] = r4[0]; b_l[2*ni][1] = r4[1];
                    b_l[2*ni+1][0] = r4[2]; b_l[2*ni+1][1] = r4[3];
                } else {
                    uint32_t bo = bB + (uint32_t)((wn + ni * 16 + (lane & 15)) * LDA_S
                                                  + kk + (lane >> 4) * 8) * 2;
                    ldsm4(r4, aBh + bo);
                    b_h[2*ni][0] = r4[0]; b_h[2*ni][1] = r4[2];
                    b_h[2*ni+1][0] = r4[1]; b_h[2*ni+1][1] = r4[3];
                    ldsm4(r4, aBl + bo);
                    b_l[2*ni][0] = r4[0]; b_l[2*ni][1] = r4[2];
                    b_l[2*ni+1][0] = r4[1]; b_l[2*ni+1][1] = r4[3];
                }
            }
            #pragma unroll
            for (int mi = 0; mi < 4; mi++)
                #pragma unroll
                for (int ni = 0; ni < 4; ni++) {
                    mma16816(acc[mi][ni], a_h[mi], b_h[ni]);
                    mma16816(acc[mi][ni], a_h[mi], b_l[ni]);
                    if (TERMS == 3) mma16816(acc[mi][ni], a_l[mi], b_h[ni]);
                }
        }
        __syncthreads();
    }

    if (OUT == 0) {
        #pragma unroll
        for (int mi = 0; mi < 4; mi++) {
            const int r0 = bm + wm + mi * 16 + (lane >> 2);
            #pragma unroll
            for (int ni = 0; ni < 4; ni++) {
                const int c = bn + wn + ni * 8 + (lane & 3) * 2;
                *reinterpret_cast<float2*>(&Cf[(long long)r0 * ldc + c]) =
                    make_float2(acc[mi][ni][0] * out_scale, acc[mi][ni][1] * out_scale);
                *reinterpret_cast<float2*>(&Cf[(long long)(r0 + 8) * ldc + c]) =
                    make_float2(acc[mi][ni][2] * out_scale, acc[mi][ni][3] * out_scale);
            }
        }
        return;
    }
    if (OUT == 4) {
        // ---- direct f16 streaming stores (evict-first; dots is read-once) ----
        #pragma unroll
        for (int mi = 0; mi < 4; mi++) {
            const int r0 = bm + wm + mi * 16 + (lane >> 2);
            #pragma unroll
            for (int ni = 0; ni < 4; ni++) {
                const int c = bn + wn + ni * 8 + (lane & 3) * 2;
                f162 p0 = __halves2half2(__float2half(acc[mi][ni][0] * out_scale),
                                         __float2half(acc[mi][ni][1] * out_scale));
                f162 p1 = __halves2half2(__float2half(acc[mi][ni][2] * out_scale),
                                         __float2half(acc[mi][ni][3] * out_scale));
                stcs32(&Ch[(long long)r0 * ldc + c], *reinterpret_cast<uint32_t*>(&p0));
                stcs32(&Ch[(long long)(r0 + 8) * ldc + c], *reinterpret_cast<uint32_t*>(&p1));
            }
        }
        return;
    }

    // ---- epilogue: regs -> smem f32 -> wide coalesced global ----
    #pragma unroll
    for (int mi = 0; mi < 4; mi++) {
        int r0 = wm + mi * 16 + (lane >> 2);
        #pragma unroll
        for (int ni = 0; ni < 4; ni++) {
            int c = wn + ni * 8 + (lane & 3) * 2;
            sE[r0 * BNP + c]           = acc[mi][ni][0];
            sE[r0 * BNP + c + 1]       = acc[mi][ni][1];
            sE[(r0 + 8) * BNP + c]     = acc[mi][ni][2];
            sE[(r0 + 8) * BNP + c + 1] = acc[mi][ni][3];
        }
    }
    __syncthreads();

    for (int i = tid; i < 128 * BN / 4; i += NT) {
        int r = i / (BN / 4), c = (i % (BN / 4)) * 4;
        float v0 = sE[r * BNP + c]     * out_scale;
        float v1 = sE[r * BNP + c + 1] * out_scale;
        float v2 = sE[r * BNP + c + 2] * out_scale;
        float v3 = sE[r * BNP + c + 3] * out_scale;
        long long go = (long long)(bm + r) * ldc + bn + c;
        if (OUT == 1) {
            *reinterpret_cast<float4*>(&Cf[go]) =
                make_float4(v0 + bias[bn + c], v1 + bias[bn + c + 1],
                            v2 + bias[bn + c + 2], v3 + bias[bn + c + 3]);
        } else if (OUT == 2) {
            f16 h0, l0, h1, l1, h2, l2, h3, l3;
            split_f16(v0, h0, l0); split_f16(v1, h1, l1);
            split_f16(v2, h2, l2); split_f16(v3, h3, l3);
            f162 hh[2] = {__halves2half2(h0, h1), __halves2half2(h2, h3)};
            f162 ll[2] = {__halves2half2(l0, l1), __halves2half2(l2, l3)};
            *reinterpret_cast<float2*>(&Ch[go]) = *reinterpret_cast<float2*>(hh);
            *reinterpret_cast<float2*>(&Cl[go]) = *reinterpret_cast<float2*>(ll);
        } else {
            f162 hh[2] = {__halves2half2(__float2half(v0), __float2half(v1)),
                          __halves2half2(__float2half(v2), __float2half(v3))};
            *reinterpret_cast<float2*>(&Ch[go]) = *reinterpret_cast<float2*>(hh);
        }
    }
}

// ------------- fused mix_pre -> softmax -> mix_post (fp16 dots in) ----------
__global__ void mix_softmax_mix2(const f16* __restrict__ dots,
                                 f16* __restrict__ ah,
                                 const float* __restrict__ pre, const float* __restrict__ post) {
    __shared__ float spre[256], spost[256], sred[16 * 16], sfin[16], sinv[16];
    const int tid = threadIdx.x;
    const int i = blockIdx.x, b = blockIdx.y;
    if (tid < 256) { spre[tid] = pre[tid]; spost[tid] = post[tid]; }
    __syncthreads();

    const long long base = (long long)b * HEADS * NSEQ * NSEQ + (long long)i * NSEQ;
    const int j0 = tid * 2;
    const int warp = tid >> 5, lane = tid & 31;

    float in0[16], in1[16];
    #pragma unroll
    for (int h = 0; h < 16; h++) {
        uint32_t u = ldcs32(&dots[base + (long long)h * NSEQ * NSEQ + j0]);
        f162 v = *reinterpret_cast<f162*>(&u);
        in0[h] = __half2float(__low2half(v));
        in1[h] = __half2float(__high2half(v));
    }

    float e0[16], e1[16];
    #pragma unroll
    for (int g = 0; g < 16; g++) {
        float m0 = 0.f, m1 = 0.f;
        #pragma unroll
        for (int h = 0; h < 16; h++) {
            float w = spre[h * 16 + g];
            m0 += in0[h] * w; m1 += in1[h] * w;
        }
        e0[g] = m0; e1[g] = m1;
    }

    #pragma unroll
    for (int g = 0; g < 16; g++) {
        float m = fmaxf(e0[g], e1[g]);
        #pragma unroll
        for (int o = 16; o; o >>= 1) m = fmaxf(m, __shfl_xor_sync(0xFFFFFFFFu, m, o));
        if (lane == 0) sred[g * 16 + warp] = m;
    }
    __syncthreads();
    if (tid < 16) {
        float m = -INFINITY;
        #pragma unroll
        for (int w = 0; w < 16; w++) m = fmaxf(m, sred[tid * 16 + w]);
        sfin[tid] = m;
    }
    __syncthreads();

    #pragma unroll
    for (int g = 0; g < 16; g++) {
        float m = sfin[g];
        e0[g] = __expf(e0[g] - m);
        e1[g] = __expf(e1[g] - m);
        float s = e0[g] + e1[g];
        #pragma unroll
        for (int o = 16; o; o >>= 1) s += __shfl_xor_sync(0xFFFFFFFFu, s, o);
        if (lane == 0) sred[g * 16 + warp] = s;
    }
    __syncthreads();
    if (tid < 16) {
        float s = 0.f;
        #pragma unroll
        for (int w = 0; w < 16; w++) s += sred[tid * 16 + w];
        sinv[tid] = 1.f / s;
    }
    __syncthreads();

    #pragma unroll
    for (int g = 0; g < 16; g++) {
        float inv = sinv[g];
        e0[g] *= inv; e1[g] *= inv;
    }

    #pragma unroll
    for (int gp = 0; gp < 16; gp++) {
        float o0 = 0.f, o1 = 0.f;
        #pragma unroll
        for (int g = 0; g < 16; g++) {
            float w = spost[g * 16 + gp];
            o0 += e0[g] * w; o1 += e1[g] * w;
        }
        long long idx = base + (long long)gp * NSEQ * NSEQ + j0;
        *reinterpret_cast<f162*>(&ah[idx]) =
            __halves2half2(__float2half(o0), __float2half(o1));
    }
}

// ---------------------------------------------------------------------------
static inline int gemm_smem(int BN, bool BT, int terms, bool direct_out) {
    int SA = 128 * 40 * (terms == 3 ? 2 : 1);
    int SB = 2 * (BT ? 32 * (BN + 8) : BN * 40);
    int pipe = 4 * (SA + SB);
    if (direct_out) return pipe;
    int epi = 128 * (BN + 4) * 4;
    return pipe > epi ? pipe : epi;
}

extern "C" void kernel_launch(void* const* d_in, const int* in_sizes, int n_in,
                              void* d_out, int out_size) {
    const float* x        = (const float*)d_in[0];
    const float* Wq       = (const float*)d_in[1];
    const float* Wkv      = (const float*)d_in[2];
    const float* mix_pre  = (const float*)d_in[3];
    const float* mix_post = (const float*)d_in[4];
    const float* Wo       = (const float*)d_in[5];
    const float* bo       = (const float*)d_in[6];
    float* out = (float*)d_out;

    f16 *xh, *xl, *wqh, *wql, *wkvh, *wkvl, *woh, *wol;
    f16 *qh, *ql, *kvh, *kvl, *ah, *mh, *dots;
    cudaGetSymbolAddress((void**)&xh, g_xh);     cudaGetSymbolAddress((void**)&xl, g_xl);
    cudaGetSymbolAddress((void**)&wqh, g_wqh);   cudaGetSymbolAddress((void**)&wql, g_wql);
    cudaGetSymbolAddress((void**)&wkvh, g_wkvh); cudaGetSymbolAddress((void**)&wkvl, g_wkvl);
    cudaGetSymbolAddress((void**)&woh, g_woh);   cudaGetSymbolAddress((void**)&wol, g_wol);
    cudaGetSymbolAddress((void**)&qh, g_qh);     cudaGetSymbolAddress((void**)&ql, g_ql);
    cudaGetSymbolAddress((void**)&kvh, g_kvh);   cudaGetSymbolAddress((void**)&kvl, g_kvl);
    cudaGetSymbolAddress((void**)&ah, g_ah);
    cudaGetSymbolAddress((void**)&mh, g_mh);
    cudaGetSymbolAddress((void**)&dots, g_dots);

    // 0) fused split of all inputs (one launch)
    split_all<<<(int)((TOT4 + 255) / 256), 256>>>(
        x, xh, xl, Wq, wqh, wql, Wkv, wkvh, wkvl, Wo, woh, wol);

    const int SM_PROJ = gemm_smem(128, true, 3, false);
    const int SM_DOTS = gemm_smem(128, false, 3, true);
    const int SM_AV   = gemm_smem(64, true, 2, false);
    const int SM_OUT  = gemm_smem(128, true, 2, false);

    cudaFuncSetAttribute((const void*)mma_gemm<128,8,true,3,2,2>,
                         cudaFuncAttributeMaxDynamicSharedMemorySize, SM_PROJ);
    cudaFuncSetAttribute((const void*)mma_gemm<128,8,false,3,4,2>,
                         cudaFuncAttributeMaxDynamicSharedMemorySize, SM_DOTS);
    cudaFuncSetAttribute((const void*)mma_gemm<64,4,true,2,3,4>,
                         cudaFuncAttributeMaxDynamicSharedMemorySize, SM_AV);
    cudaFuncSetAttribute((const void*)mma_gemm<128,8,true,2,1,2>,
                         cudaFuncAttributeMaxDynamicSharedMemorySize, SM_OUT);

    // 1) q = SCALE * (x @ Wq) -> split hi/lo   (3-term)
    mma_gemm<128,8,true,3,2,2><<<dim3(8, 32, 1), 256, SM_PROJ>>>(
        xh, xl, wqh, wql, nullptr, qh, ql, nullptr,
        DIM, DIM, INNER, INNER, 0, 0, 0, 0, 0, 0, SCALE);

    // 2) kv = x @ Wkv -> split hi/lo           (3-term)
    mma_gemm<128,8,true,3,2,2><<<dim3(16, 32, 1), 256, SM_PROJ>>>(
        xh, xl, wkvh, wkvl, nullptr, kvh, kvl, nullptr,
        DIM, DIM, 2 * INNER, 2 * INNER, 0, 0, 0, 0, 0, 0, 1.f);

    // 3) dots = q @ k^T -> f16 direct streaming stores, z=(b,h)  (3-term)
    mma_gemm<128,8,false,3,4,2><<<dim3(8, 8, BATCH * HEADS), 256, SM_DOTS>>>(
        qh, ql, kvh, kvl, nullptr, dots, nullptr, nullptr,
        DHEAD, INNER, 2 * INNER, NSEQ,
        (long long)NSEQ * INNER, DHEAD,
        (long long)NSEQ * 2 * INNER, DHEAD,
        (long long)HEADS * NSEQ * NSEQ, (long long)NSEQ * NSEQ, 1.f);

    // 4) mix_pre -> softmax -> mix_post -> attn hi (fp16)
    mix_softmax_mix2<<<dim3(NSEQ, BATCH), 512>>>(dots, ah, mix_pre, mix_post);

    // 5) mid = attn @ v -> hi only, batched z=(b,g)  (2-term, OCC=4)
    mma_gemm<64,4,true,2,3,4><<<dim3(1, 8, BATCH * HEADS), 128, SM_AV>>>(
        ah, nullptr, kvh + INNER, kvl + INNER, nullptr, mh, nullptr, nullptr,
        NSEQ, NSEQ, 2 * INNER, INNER,
        (long long)HEADS * NSEQ * NSEQ, (long long)NSEQ * NSEQ,
        (long long)NSEQ * 2 * INNER, DHEAD,
        (long long)NSEQ * INNER, DHEAD, 1.f);

    // 6) out = mid @ Wo + bo -> f32             (2-term)
    mma_gemm<128,8,true,2,1,2><<<dim3(8, 32, 1), 256, SM_OUT>>>(
        mh, nullptr, woh, wol, out, nullptr, nullptr, bo,
        INNER, INNER, DIM, DIM, 0, 0, 0, 0, 0, 0, 1.f);
}

// round 16
// speedup vs baseline: 1.0090x; 1.0090x over previous
#include <cuda_runtime.h>
#include <cuda_fp16.h>
#include <math.h>
#include <cstdint>

#define BATCH 4
#define NSEQ 1024
#define DIM 1024
#define HEADS 16
#define DHEAD 64
#define INNER 1024
#define SCALE 0.125f

typedef __half f16;
typedef __half2 f162;

// ---------------- scratch (device globals; allocation-free) ----------------
#define NELEM_X   ((long long)BATCH * NSEQ * DIM)
#define NELEM_WQ  ((long long)DIM * INNER)
#define NELEM_WKV ((long long)DIM * 2 * INNER)
#define NELEM_WO  ((long long)INNER * DIM)
#define NELEM_Q   ((long long)BATCH * NSEQ * INNER)
#define NELEM_KV  ((long long)BATCH * NSEQ * 2 * INNER)
#define NELEM_ATT ((long long)BATCH * HEADS * NSEQ * NSEQ)

__device__ f16 g_xh[NELEM_X],   g_xl[NELEM_X];
__device__ f16 g_wqh[NELEM_WQ], g_wql[NELEM_WQ];
__device__ f16 g_wkvh[NELEM_WKV], g_wkvl[NELEM_WKV];
__device__ f16 g_woh[NELEM_WO], g_wol[NELEM_WO];
__device__ f16 g_qh[NELEM_Q],   g_ql[NELEM_Q];
__device__ f16 g_kvh[NELEM_KV], g_kvl[NELEM_KV];
__device__ float g_dots[NELEM_ATT];     // f32, 256 MB
__device__ f16 g_ah[NELEM_ATT];         // attn hi only
__device__ f16 g_mh[NELEM_Q];           // mid hi only

__device__ __forceinline__ void split_f16(float x, f16& h, f16& l) {
    h = __float2half(x);
    l = __float2half(x - __half2float(h));
}
__device__ __forceinline__ void cp16(uint32_t s, const void* g) {
    asm volatile("cp.async.cg.shared.global [%0], [%1], 16;" :: "r"(s), "l"(g));
}
__device__ __forceinline__ void cp_commit() { asm volatile("cp.async.commit_group;"); }
template<int N>
__device__ __forceinline__ void cp_wait() { asm volatile("cp.async.wait_group %0;" :: "n"(N)); }

__device__ __forceinline__ void ldsm4(uint32_t* r, uint32_t a) {
    asm volatile("ldmatrix.sync.aligned.m8n8.x4.shared.b16 {%0,%1,%2,%3}, [%4];"
                 : "=r"(r[0]), "=r"(r[1]), "=r"(r[2]), "=r"(r[3]) : "r"(a));
}
__device__ __forceinline__ void ldsm4t(uint32_t* r, uint32_t a) {
    asm volatile("ldmatrix.sync.aligned.m8n8.x4.trans.shared.b16 {%0,%1,%2,%3}, [%4];"
                 : "=r"(r[0]), "=r"(r[1]), "=r"(r[2]), "=r"(r[3]) : "r"(a));
}
__device__ __forceinline__ void mma16816(float* c, const uint32_t* a, const uint32_t* b) {
    asm volatile("mma.sync.aligned.m16n8k16.row.col.f32.f16.f16.f32 "
                 "{%0,%1,%2,%3}, {%4,%5,%6,%7}, {%8,%9}, {%0,%1,%2,%3};"
                 : "+f"(c[0]), "+f"(c[1]), "+f"(c[2]), "+f"(c[3])
                 : "r"(a[0]), "r"(a[1]), "r"(a[2]), "r"(a[3]), "r"(b[0]), "r"(b[1]));
}

// ---------------- fused split: all four f32 inputs -> f16 hi/lo -------------
#define X4   (NELEM_X / 4)
#define WQ4  (NELEM_WQ / 4)
#define WKV4 (NELEM_WKV / 4)
#define WO4  (NELEM_WO / 4)
#define TOT4 (X4 + WQ4 + WKV4 + WO4)

__global__ void split_all(const float* __restrict__ x,
                          const float* __restrict__ wq,
                          const float* __restrict__ wkv,
                          const float* __restrict__ wo) {
    long long i = (long long)blockIdx.x * blockDim.x + threadIdx.x;
    if (i >= TOT4) return;
    const float* in; f16 *hi, *lo; long long o;
    if (i < X4)                    { in = x;   hi = g_xh;   lo = g_xl;   o = i; }
    else if (i < X4 + WQ4)         { in = wq;  hi = g_wqh;  lo = g_wql;  o = i - X4; }
    else if (i < X4 + WQ4 + WKV4)  { in = wkv; hi = g_wkvh; lo = g_wkvl; o = i - X4 - WQ4; }
    else                           { in = wo;  hi = g_woh;  lo = g_wol;  o = i - X4 - WQ4 - WKV4; }
    float4 v = reinterpret_cast<const float4*>(in)[o];
    f16 h0, l0, h1, l1, h2, l2, h3, l3;
    split_f16(v.x, h0, l0); split_f16(v.y, h1, l1);
    split_f16(v.z, h2, l2); split_f16(v.w, h3, l3);
    reinterpret_cast<f162*>(hi)[o * 2]     = __halves2half2(h0, h1);
    reinterpret_cast<f162*>(hi)[o * 2 + 1] = __halves2half2(h2, h3);
    reinterpret_cast<f162*>(lo)[o * 2]     = __halves2half2(l0, l1);
    reinterpret_cast<f162*>(lo)[o * 2 + 1] = __halves2half2(l2, l3);
}

// ---------------------------------------------------------------------------
// Raw mma.sync fp16 split GEMM, 2-buffer cp.async pipeline, OCC CTAs/SM.
//   TERMS=3: acc = Ah(Bh+Bl) + Al·Bh.   TERMS=2: acc = Ah(Bh+Bl).
//   BTRANS=false: B [N,K] row-major (ldmatrix).  true: B [K,N] (ldmatrix.trans).
//   OUT: 0 f32 direct, 1 f32+bias smem, 2 split f16 hi/lo smem, 3 f16 hi smem.
//   MERGED_PROJ: grid.x=24; bx<8 -> q=SCALE*x@Wq, bx>=8 -> kv=x@Wkv (globals).
// ---------------------------------------------------------------------------
template<int BN, int NWARP, bool BTRANS, int TERMS, int OUT, int OCC, bool MERGED_PROJ>
__global__ void __launch_bounds__(NWARP * 32, OCC)
mma_gemm(const f16* __restrict__ Ah, const f16* __restrict__ Al,
         const f16* __restrict__ Bh_, const f16* __restrict__ Bl_,
         float* __restrict__ Cf, f16* __restrict__ Ch_, f16* __restrict__ Cl_,
         const float* __restrict__ bias,
         int K, int lda, int ldb_, int ldc_,
         long long sa_b, long long sa_h,
         long long sb_b, long long sb_h,
         long long sc_b, long long sc_h,
         float out_scale_)
{
    constexpr int NT = NWARP * 32;
    constexpr int WARPS_N = BN / 32;
    constexpr int LDA_S = 40;
    constexpr int LDBT = BN + 8;
    constexpr int SA_E = 128 * LDA_S;
    constexpr int SB_E = BTRANS ? 32 * LDBT : BN * LDA_S;
    constexpr int NAH = (TERMS == 3) ? 2 : 1;
    constexpr int BNP = BN + 4;

    extern __shared__ char smem[];
    const uint32_t aAh = (uint32_t)__cvta_generic_to_shared(smem);
    const uint32_t aAl = aAh + 2 * SA_E * 2;
    const uint32_t aBh = aAh + 2 * SA_E * 2 * NAH;
    const uint32_t aBl = aBh + 2 * SB_E * 2;
    float* sE = reinterpret_cast<float*>(smem);

    const int tid = threadIdx.x;
    const int warp = tid >> 5, lane = tid & 31;
    const int wm = (warp / WARPS_N) * 64;
    const int wn = (warp % WARPS_N) * 32;

    // resolve operands (merged-proj overrides via globals)
    const f16* Bh = Bh_;
    const f16* Bl = Bl_;
    f16* Ch = Ch_;
    f16* Cl = Cl_;
    int ldb = ldb_, ldc = ldc_;
    float out_scale = out_scale_;
    int bn;
    if (MERGED_PROJ) {
        if (blockIdx.x < 8) {
            Bh = g_wqh; Bl = g_wql; Ch = g_qh; Cl = g_ql;
            ldb = INNER; ldc = INNER; out_scale = SCALE;
            bn = blockIdx.x * BN;
        } else {
            Bh = g_wkvh; Bl = g_wkvl; Ch = g_kvh; Cl = g_kvl;
            ldb = 2 * INNER; ldc = 2 * INNER; out_scale = 1.f;
            bn = (blockIdx.x - 8) * BN;
        }
    } else {
        bn = blockIdx.x * BN;
    }

    const int z = blockIdx.z, zb = z >> 4, zh = z & 15;
    Ah += zb * sa_b + zh * sa_h;
    if (TERMS == 3) Al += zb * sa_b + zh * sa_h;
    if (!MERGED_PROJ) {
        Bh += zb * sb_b + zh * sb_h;  Bl += zb * sb_b + zh * sb_h;
        if (OUT >= 2) { Ch += zb * sc_b + zh * sc_h; if (OUT == 2) Cl += zb * sc_b + zh * sc_h; }
        else          { Cf += zb * sc_b + zh * sc_h; }
    }

    const int bm = blockIdx.y * 128;

    float acc[4][4][4] = {};

    auto load_stage = [&](int s) {
        const int buf = s & 1;
        const int k0 = s * 32;
        const uint32_t bA = (uint32_t)buf * SA_E * 2;
        const uint32_t bB = (uint32_t)buf * SB_E * 2;
        #pragma unroll
        for (int c = tid; c < 512; c += NT) {
            int r = c >> 2, ck = (c & 3) * 8;
            long long g = (long long)(bm + r) * lda + k0 + ck;
            uint32_t so = bA + (uint32_t)(r * LDA_S + ck) * 2;
            cp16(aAh + so, Ah + g);
            if (TERMS == 3) cp16(aAl + so, Al + g);
        }
        if (BTRANS) {
            #pragma unroll
            for (int c = tid; c < 32 * (BN / 8); c += NT) {
                int kr = c / (BN / 8), nc = (c % (BN / 8)) * 8;
                long long g = (long long)(k0 + kr) * ldb + bn + nc;
                uint32_t so = bB + (uint32_t)(kr * LDBT + nc) * 2;
                cp16(aBh + so, Bh + g);
                cp16(aBl + so, Bl + g);
            }
        } else {
            #pragma unroll
            for (int c = tid; c < BN * 4; c += NT) {
                int r = c >> 2, ck = (c & 3) * 8;
                long long g = (long long)(bn + r) * ldb + k0 + ck;
                uint32_t so = bB + (uint32_t)(r * LDA_S + ck) * 2;
                cp16(aBh + so, Bh + g);
                cp16(aBl + so, Bl + g);
            }
        }
        cp_commit();
    };

    const int S = K / 32;
    load_stage(0);

    for (int s = 0; s < S; s++) {
        cp_wait<0>();
        __syncthreads();
        if (s + 1 < S) load_stage(s + 1);

        const int buf = s & 1;
        const uint32_t bA = (uint32_t)buf * SA_E * 2;
        const uint32_t bB = (uint32_t)buf * SB_E * 2;

        #pragma unroll
        for (int kk = 0; kk < 32; kk += 16) {
            uint32_t a_h[4][4], a_l[4][4];
            #pragma unroll
            for (int mi = 0; mi < 4; mi++) {
                uint32_t ao = bA + (uint32_t)((wm + mi * 16 + (lane & 15)) * LDA_S
                                              + kk + (lane >> 4) * 8) * 2;
                ldsm4(a_h[mi], aAh + ao);
                if (TERMS == 3) ldsm4(a_l[mi], aAl + ao);
            }
            uint32_t b_h[4][2], b_l[4][2];
            #pragma unroll
            for (int ni = 0; ni < 2; ni++) {
                uint32_t r4[4];
                if (BTRANS) {
                    uint32_t bo = bB + (uint32_t)((kk + (lane & 15)) * LDBT
                                                  + wn + ni * 16 + (lane >> 4) * 8) * 2;
                    ldsm4t(r4, aBh + bo);
                    b_h[2*ni][0] = r4[0]; b_h[2*ni][1] = r4[1];
                    b_h[2*ni+1][0] = r4[2]; b_h[2*ni+1][1] = r4[3];
                    ldsm4t(r4, aBl + bo);
                    b_l[2*ni][0] = r4[0]; b_l[2*ni][1] = r4[1];
                    b_l[2*ni+1][0] = r4[2]; b_l[2*ni+1][1] = r4[3];
                } else {
                    uint32_t bo = bB + (uint32_t)((wn + ni * 16 + (lane & 15)) * LDA_S
                                                  + kk + (lane >> 4) * 8) * 2;
                    ldsm4(r4, aBh + bo);
                    b_h[2*ni][0] = r4[0]; b_h[2*ni][1] = r4[2];
                    b_h[2*ni+1][0] = r4[1]; b_h[2*ni+1][1] = r4[3];
                    ldsm4(r4, aBl + bo);
                    b_l[2*ni][0] = r4[0]; b_l[2*ni][1] = r4[2];
                    b_l[2*ni+1][0] = r4[1]; b_l[2*ni+1][1] = r4[3];
                }
            }
            #pragma unroll
            for (int mi = 0; mi < 4; mi++)
                #pragma unroll
                for (int ni = 0; ni < 4; ni++) {
                    mma16816(acc[mi][ni], a_h[mi], b_h[ni]);
                    mma16816(acc[mi][ni], a_h[mi], b_l[ni]);
                    if (TERMS == 3) mma16816(acc[mi][ni], a_l[mi], b_h[ni]);
                }
        }
        __syncthreads();
    }

    if (OUT == 0) {
        // ---- direct register -> global f32 stores ----
        #pragma unroll
        for (int mi = 0; mi < 4; mi++) {
            const int r0 = bm + wm + mi * 16 + (lane >> 2);
            #pragma unroll
            for (int ni = 0; ni < 4; ni++) {
                const int c = bn + wn + ni * 8 + (lane & 3) * 2;
                *reinterpret_cast<float2*>(&Cf[(long long)r0 * ldc + c]) =
                    make_float2(acc[mi][ni][0] * out_scale, acc[mi][ni][1] * out_scale);
                *reinterpret_cast<float2*>(&Cf[(long long)(r0 + 8) * ldc + c]) =
                    make_float2(acc[mi][ni][2] * out_scale, acc[mi][ni][3] * out_scale);
            }
        }
        return;
    }

    // ---- epilogue: regs -> smem f32 -> wide coalesced global ----
    #pragma unroll
    for (int mi = 0; mi < 4; mi++) {
        int r0 = wm + mi * 16 + (lane >> 2);
        #pragma unroll
        for (int ni = 0; ni < 4; ni++) {
            int c = wn + ni * 8 + (lane & 3) * 2;
            sE[r0 * BNP + c]           = acc[mi][ni][0];
            sE[r0 * BNP + c + 1]       = acc[mi][ni][1];
            sE[(r0 + 8) * BNP + c]     = acc[mi][ni][2];
            sE[(r0 + 8) * BNP + c + 1] = acc[mi][ni][3];
        }
    }
    __syncthreads();

    for (int i = tid; i < 128 * BN / 4; i += NT) {
        int r = i / (BN / 4), c = (i % (BN / 4)) * 4;
        float v0 = sE[r * BNP + c]     * out_scale;
        float v1 = sE[r * BNP + c + 1] * out_scale;
        float v2 = sE[r * BNP + c + 2] * out_scale;
        float v3 = sE[r * BNP + c + 3] * out_scale;
        long long go = (long long)(bm + r) * ldc + bn + c;
        if (OUT == 1) {
            *reinterpret_cast<float4*>(&Cf[go]) =
                make_float4(v0 + bias[bn + c], v1 + bias[bn + c + 1],
                            v2 + bias[bn + c + 2], v3 + bias[bn + c + 3]);
        } else if (OUT == 2) {
            f16 h0, l0, h1, l1, h2, l2, h3, l3;
            split_f16(v0, h0, l0); split_f16(v1, h1, l1);
            split_f16(v2, h2, l2); split_f16(v3, h3, l3);
            f162 hh[2] = {__halves2half2(h0, h1), __halves2half2(h2, h3)};
            f162 ll[2] = {__halves2half2(l0, l1), __halves2half2(l2, l3)};
            *reinterpret_cast<float2*>(&Ch[go]) = *reinterpret_cast<float2*>(hh);
            *reinterpret_cast<float2*>(&Cl[go]) = *reinterpret_cast<float2*>(ll);
        } else {
            f162 hh[2] = {__halves2half2(__float2half(v0), __float2half(v1)),
                          __halves2half2(__float2half(v2), __float2half(v3))};
            *reinterpret_cast<float2*>(&Ch[go]) = *reinterpret_cast<float2*>(hh);
        }
    }
}

// ------------- fused mix_pre -> softmax -> mix_post (proven mix2, f32 in) ---
__global__ void mix_softmax_mix2(const float* __restrict__ dots,
                                 f16* __restrict__ ah,
                                 const float* __restrict__ pre, const float* __restrict__ post) {
    __shared__ float spre[256], spost[256], sred[16 * 16], sfin[16], sinv[16];
    const int tid = threadIdx.x;
    const int i = blockIdx.x, b = blockIdx.y;
    if (tid < 256) { spre[tid] = pre[tid]; spost[tid] = post[tid]; }
    __syncthreads();

    const long long base = (long long)b * HEADS * NSEQ * NSEQ + (long long)i * NSEQ;
    const int j0 = tid * 2;
    const int warp = tid >> 5, lane = tid & 31;

    float in0[16], in1[16];
    #pragma unroll
    for (int h = 0; h < 16; h++) {
        float2 v = *reinterpret_cast<const float2*>(&dots[base + (long long)h * NSEQ * NSEQ + j0]);
        in0[h] = v.x; in1[h] = v.y;
    }

    float e0[16], e1[16];
    #pragma unroll
    for (int g = 0; g < 16; g++) {
        float m0 = 0.f, m1 = 0.f;
        #pragma unroll
        for (int h = 0; h < 16; h++) {
            float w = spre[h * 16 + g];
            m0 += in0[h] * w; m1 += in1[h] * w;
        }
        e0[g] = m0; e1[g] = m1;
    }

    #pragma unroll
    for (int g = 0; g < 16; g++) {
        float m = fmaxf(e0[g], e1[g]);
        #pragma unroll
        for (int o = 16; o; o >>= 1) m = fmaxf(m, __shfl_xor_sync(0xFFFFFFFFu, m, o));
        if (lane == 0) sred[g * 16 + warp] = m;
    }
    __syncthreads();
    if (tid < 16) {
        float m = -INFINITY;
        #pragma unroll
        for (int w = 0; w < 16; w++) m = fmaxf(m, sred[tid * 16 + w]);
        sfin[tid] = m;
    }
    __syncthreads();

    #pragma unroll
    for (int g = 0; g < 16; g++) {
        float m = sfin[g];
        e0[g] = __expf(e0[g] - m);
        e1[g] = __expf(e1[g] - m);
        float s = e0[g] + e1[g];
        #pragma unroll
        for (int o = 16; o; o >>= 1) s += __shfl_xor_sync(0xFFFFFFFFu, s, o);
        if (lane == 0) sred[g * 16 + warp] = s;
    }
    __syncthreads();
    if (tid < 16) {
        float s = 0.f;
        #pragma unroll
        for (int w = 0; w < 16; w++) s += sred[tid * 16 + w];
        sinv[tid] = 1.f / s;
    }
    __syncthreads();

    #pragma unroll
    for (int g = 0; g < 16; g++) {
        float inv = sinv[g];
        e0[g] *= inv; e1[g] *= inv;
    }

    #pragma unroll
    for (int gp = 0; gp < 16; gp++) {
        float o0 = 0.f, o1 = 0.f;
        #pragma unroll
        for (int g = 0; g < 16; g++) {
            float w = spost[g * 16 + gp];
            o0 += e0[g] * w; o1 += e1[g] * w;
        }
        long long idx = base + (long long)gp * NSEQ * NSEQ + j0;
        *reinterpret_cast<f162*>(&ah[idx]) =
            __halves2half2(__float2half(o0), __float2half(o1));
    }
}

// ---------------------------------------------------------------------------
static inline int gemm_smem(int BN, bool BT, int terms, bool direct_out) {
    int SA = 128 * 40 * (terms == 3 ? 2 : 1);
    int SB = 2 * (BT ? 32 * (BN + 8) : BN * 40);
    int pipe = 4 * (SA + SB);
    if (direct_out) return pipe;
    int epi = 128 * (BN + 4) * 4;
    return pipe > epi ? pipe : epi;
}

extern "C" void kernel_launch(void* const* d_in, const int* in_sizes, int n_in,
                              void* d_out, int out_size) {
    const float* x        = (const float*)d_in[0];
    const float* Wq       = (const float*)d_in[1];
    const float* Wkv      = (const float*)d_in[2];
    const float* mix_pre  = (const float*)d_in[3];
    const float* mix_post = (const float*)d_in[4];
    const float* Wo       = (const float*)d_in[5];
    const float* bo       = (const float*)d_in[6];
    float* out = (float*)d_out;

    f16 *xh, *xl, *woh, *wol, *kvh, *kvl, *ah, *mh, *qh, *ql;
    float* dots;
    cudaGetSymbolAddress((void**)&xh, g_xh);     cudaGetSymbolAddress((void**)&xl, g_xl);
    cudaGetSymbolAddress((void**)&woh, g_woh);   cudaGetSymbolAddress((void**)&wol, g_wol);
    cudaGetSymbolAddress((void**)&qh, g_qh);     cudaGetSymbolAddress((void**)&ql, g_ql);
    cudaGetSymbolAddress((void**)&kvh, g_kvh);   cudaGetSymbolAddress((void**)&kvl, g_kvl);
    cudaGetSymbolAddress((void**)&ah, g_ah);
    cudaGetSymbolAddress((void**)&mh, g_mh);
    cudaGetSymbolAddress((void**)&dots, g_dots);

    // 0) fused split of all inputs (one launch; outputs via device globals)
    split_all<<<(int)((TOT4 + 255) / 256), 256>>>(x, Wq, Wkv, Wo);

    const int SM_PROJ = gemm_smem(128, true, 3, false);
    const int SM_DOTS = gemm_smem(128, false, 3, true);
    const int SM_AV   = gemm_smem(64, true, 2, false);
    const int SM_OUT  = gemm_smem(128, true, 2, false);

    cudaFuncSetAttribute((const void*)mma_gemm<128,8,true,3,2,2,true>,
                         cudaFuncAttributeMaxDynamicSharedMemorySize, SM_PROJ);
    cudaFuncSetAttribute((const void*)mma_gemm<128,8,false,3,0,2,false>,
                         cudaFuncAttributeMaxDynamicSharedMemorySize, SM_DOTS);
    cudaFuncSetAttribute((const void*)mma_gemm<64,4,true,2,3,4,false>,
                         cudaFuncAttributeMaxDynamicSharedMemorySize, SM_AV);
    cudaFuncSetAttribute((const void*)mma_gemm<128,8,true,2,1,2,false>,
                         cudaFuncAttributeMaxDynamicSharedMemorySize, SM_OUT);

    // 1+2) merged projections: bx<8 -> q (SCALE), bx>=8 -> kv   (3-term)
    mma_gemm<128,8,true,3,2,2,true><<<dim3(24, 32, 1), 256, SM_PROJ>>>(
        xh, xl, nullptr, nullptr, nullptr, nullptr, nullptr, nullptr,
        DIM, DIM, 0, 0, 0, 0, 0, 0, 0, 0, 0.f);

    // 3) dots = q @ k^T -> f32 direct stores, z=(b,h)  (3-term)
    mma_gemm<128,8,false,3,0,2,false><<<dim3(8, 8, BATCH * HEADS), 256, SM_DOTS>>>(
        qh, ql, kvh, kvl, dots, nullptr, nullptr, nullptr,
        DHEAD, INNER, 2 * INNER, NSEQ,
        (long long)NSEQ * INNER, DHEAD,
        (long long)NSEQ * 2 * INNER, DHEAD,
        (long long)HEADS * NSEQ * NSEQ, (long long)NSEQ * NSEQ, 1.f);

    // 4) mix_pre -> softmax -> mix_post -> attn hi (fp16)
    mix_softmax_mix2<<<dim3(NSEQ, BATCH), 512>>>(dots, ah, mix_pre, mix_post);

    // 5) mid = attn @ v -> hi only, batched z=(b,g)  (2-term, OCC=4)
    mma_gemm<64,4,true,2,3,4,false><<<dim3(1, 8, BATCH * HEADS), 128, SM_AV>>>(
        ah, nullptr, kvh + INNER, kvl + INNER, nullptr, mh, nullptr, nullptr,
        NSEQ, NSEQ, 2 * INNER, INNER,
        (long long)HEADS * NSEQ * NSEQ, (long long)NSEQ * NSEQ,
        (long long)NSEQ * 2 * INNER, DHEAD,
        (long long)NSEQ * INNER, DHEAD, 1.f);

    // 6) out = mid @ Wo + bo -> f32             (2-term)
    mma_gemm<128,8,true,2,1,2,false><<<dim3(8, 32, 1), 256, SM_OUT>>>(
        mh, nullptr, woh, wol, out, nullptr, nullptr, bo,
        INNER, INNER, DIM, DIM, 0, 0, 0, 0, 0, 0, 1.f);
}

// round 17
// speedup vs baseline: 1.1163x; 1.1064x over previous
#include <cuda_runtime.h>
#include <cuda_fp16.h>
#include <math.h>
#include <cstdint>

#define BATCH 4
#define NSEQ 1024
#define DIM 1024
#define HEADS 16
#define DHEAD 64
#define INNER 1024
#define SCALE 0.125f

typedef __half f16;
typedef __half2 f162;

// ---------------- scratch (device globals; allocation-free) ----------------
#define NELEM_X   ((long long)BATCH * NSEQ * DIM)
#define NELEM_WQ  ((long long)DIM * INNER)
#define NELEM_WKV ((long long)DIM * 2 * INNER)
#define NELEM_WO  ((long long)INNER * DIM)
#define NELEM_Q   ((long long)BATCH * NSEQ * INNER)
#define NELEM_KV  ((long long)BATCH * NSEQ * 2 * INNER)
#define NELEM_ATT ((long long)BATCH * HEADS * NSEQ * NSEQ)

__device__ f16 g_xh[NELEM_X],   g_xl[NELEM_X];
__device__ f16 g_wqh[NELEM_WQ], g_wql[NELEM_WQ];
__device__ f16 g_wkvh[NELEM_WKV], g_wkvl[NELEM_WKV];
__device__ f16 g_woh[NELEM_WO], g_wol[NELEM_WO];
__device__ f16 g_qh[NELEM_Q],   g_ql[NELEM_Q];
__device__ f16 g_kvh[NELEM_KV], g_kvl[NELEM_KV];
__device__ float g_dots[NELEM_ATT];     // f32, 256 MB
__device__ f16 g_ah[NELEM_ATT];         // attn hi only
__device__ f16 g_mh[NELEM_Q];           // mid hi only

__device__ __forceinline__ void split_f16(float x, f16& h, f16& l) {
    h = __float2half(x);
    l = __float2half(x - __half2float(h));
}
__device__ __forceinline__ void cp16(uint32_t s, const void* g) {
    asm volatile("cp.async.cg.shared.global [%0], [%1], 16;" :: "r"(s), "l"(g));
}
__device__ __forceinline__ void cp_commit() { asm volatile("cp.async.commit_group;"); }
template<int N>
__device__ __forceinline__ void cp_wait() { asm volatile("cp.async.wait_group %0;" :: "n"(N)); }

__device__ __forceinline__ void ldsm4(uint32_t* r, uint32_t a) {
    asm volatile("ldmatrix.sync.aligned.m8n8.x4.shared.b16 {%0,%1,%2,%3}, [%4];"
                 : "=r"(r[0]), "=r"(r[1]), "=r"(r[2]), "=r"(r[3]) : "r"(a));
}
__device__ __forceinline__ void ldsm4t(uint32_t* r, uint32_t a) {
    asm volatile("ldmatrix.sync.aligned.m8n8.x4.trans.shared.b16 {%0,%1,%2,%3}, [%4];"
                 : "=r"(r[0]), "=r"(r[1]), "=r"(r[2]), "=r"(r[3]) : "r"(a));
}
__device__ __forceinline__ void mma16816(float* c, const uint32_t* a, const uint32_t* b) {
    asm volatile("mma.sync.aligned.m16n8k16.row.col.f32.f16.f16.f32 "
                 "{%0,%1,%2,%3}, {%4,%5,%6,%7}, {%8,%9}, {%0,%1,%2,%3};"
                 : "+f"(c[0]), "+f"(c[1]), "+f"(c[2]), "+f"(c[3])
                 : "r"(a[0]), "r"(a[1]), "r"(a[2]), "r"(a[3]), "r"(b[0]), "r"(b[1]));
}

// ---------------- fused split: all four f32 inputs -> f16 hi/lo -------------
#define X4   (NELEM_X / 4)
#define WQ4  (NELEM_WQ / 4)
#define WKV4 (NELEM_WKV / 4)
#define WO4  (NELEM_WO / 4)
#define TOT4 (X4 + WQ4 + WKV4 + WO4)

__global__ void split_all(const float* __restrict__ x,
                          const float* __restrict__ wq,
                          const float* __restrict__ wkv,
                          const float* __restrict__ wo) {
    long long i = (long long)blockIdx.x * blockDim.x + threadIdx.x;
    if (i >= TOT4) return;
    const float* in; f16 *hi, *lo; long long o;
    if (i < X4)                    { in = x;   hi = g_xh;   lo = g_xl;   o = i; }
    else if (i < X4 + WQ4)         { in = wq;  hi = g_wqh;  lo = g_wql;  o = i - X4; }
    else if (i < X4 + WQ4 + WKV4)  { in = wkv; hi = g_wkvh; lo = g_wkvl; o = i - X4 - WQ4; }
    else                           { in = wo;  hi = g_woh;  lo = g_wol;  o = i - X4 - WQ4 - WKV4; }
    float4 v = reinterpret_cast<const float4*>(in)[o];
    f16 h0, l0, h1, l1, h2, l2, h3, l3;
    split_f16(v.x, h0, l0); split_f16(v.y, h1, l1);
    split_f16(v.z, h2, l2); split_f16(v.w, h3, l3);
    reinterpret_cast<f162*>(hi)[o * 2]     = __halves2half2(h0, h1);
    reinterpret_cast<f162*>(hi)[o * 2 + 1] = __halves2half2(h2, h3);
    reinterpret_cast<f162*>(lo)[o * 2]     = __halves2half2(l0, l1);
    reinterpret_cast<f162*>(lo)[o * 2 + 1] = __halves2half2(l2, l3);
}

// ---------------------------------------------------------------------------
// Raw mma.sync fp16 split GEMM, 2-buffer cp.async pipeline, OCC CTAs/SM.
//   TERMS=3: acc = Ah(Bh+Bl) + Al·Bh.   TERMS=2: acc = Ah(Bh+Bl).
//   BTRANS=false: B [N,K] row-major (ldmatrix).  true: B [K,N] (ldmatrix.trans).
//   OUT: 0 f32 direct, 1 f32+bias smem, 2 split f16 hi/lo smem, 3 f16 hi smem.
//   MERGED_PROJ: grid.x=24; bx<8 -> q=SCALE*x@Wq, bx>=8 -> kv=x@Wkv (globals).
// ---------------------------------------------------------------------------
template<int BN, int NWARP, bool BTRANS, int TERMS, int OUT, int OCC, bool MERGED_PROJ>
__global__ void __launch_bounds__(NWARP * 32, OCC)
mma_gemm(const f16* __restrict__ Ah, const f16* __restrict__ Al,
         const f16* __restrict__ Bh_, const f16* __restrict__ Bl_,
         float* __restrict__ Cf, f16* __restrict__ Ch_, f16* __restrict__ Cl_,
         const float* __restrict__ bias,
         int K, int lda, int ldb_, int ldc_,
         long long sa_b, long long sa_h,
         long long sb_b, long long sb_h,
         long long sc_b, long long sc_h,
         float out_scale_)
{
    constexpr int NT = NWARP * 32;
    constexpr int WARPS_N = BN / 32;
    constexpr int LDA_S = 40;
    constexpr int LDBT = BN + 8;
    constexpr int SA_E = 128 * LDA_S;
    constexpr int SB_E = BTRANS ? 32 * LDBT : BN * LDA_S;
    constexpr int NAH = (TERMS == 3) ? 2 : 1;
    constexpr int BNP = BN + 4;

    extern __shared__ char smem[];
    const uint32_t aAh = (uint32_t)__cvta_generic_to_shared(smem);
    const uint32_t aAl = aAh + 2 * SA_E * 2;
    const uint32_t aBh = aAh + 2 * SA_E * 2 * NAH;
    const uint32_t aBl = aBh + 2 * SB_E * 2;
    float* sE = reinterpret_cast<float*>(smem);

    const int tid = threadIdx.x;
    const int warp = tid >> 5, lane = tid & 31;
    const int wm = (warp / WARPS_N) * 64;
    const int wn = (warp % WARPS_N) * 32;

    const f16* Bh = Bh_;
    const f16* Bl = Bl_;
    f16* Ch = Ch_;
    f16* Cl = Cl_;
    int ldb = ldb_, ldc = ldc_;
    float out_scale = out_scale_;
    int bn;
    if (MERGED_PROJ) {
        if (blockIdx.x < 8) {
            Bh = g_wqh; Bl = g_wql; Ch = g_qh; Cl = g_ql;
            ldb = INNER; ldc = INNER; out_scale = SCALE;
            bn = blockIdx.x * BN;
        } else {
            Bh = g_wkvh; Bl = g_wkvl; Ch = g_kvh; Cl = g_kvl;
            ldb = 2 * INNER; ldc = 2 * INNER; out_scale = 1.f;
            bn = (blockIdx.x - 8) * BN;
        }
    } else {
        bn = blockIdx.x * BN;
    }

    const int z = blockIdx.z, zb = z >> 4, zh = z & 15;
    Ah += zb * sa_b + zh * sa_h;
    if (TERMS == 3) Al += zb * sa_b + zh * sa_h;
    if (!MERGED_PROJ) {
        Bh += zb * sb_b + zh * sb_h;  Bl += zb * sb_b + zh * sb_h;
        if (OUT >= 2) { Ch += zb * sc_b + zh * sc_h; if (OUT == 2) Cl += zb * sc_b + zh * sc_h; }
        else          { Cf += zb * sc_b + zh * sc_h; }
    }

    const int bm = blockIdx.y * 128;

    float acc[4][4][4] = {};

    auto load_stage = [&](int s) {
        const int buf = s & 1;
        const int k0 = s * 32;
        const uint32_t bA = (uint32_t)buf * SA_E * 2;
        const uint32_t bB = (uint32_t)buf * SB_E * 2;
        #pragma unroll
        for (int c = tid; c < 512; c += NT) {
            int r = c >> 2, ck = (c & 3) * 8;
            long long g = (long long)(bm + r) * lda + k0 + ck;
            uint32_t so = bA + (uint32_t)(r * LDA_S + ck) * 2;
            cp16(aAh + so, Ah + g);
            if (TERMS == 3) cp16(aAl + so, Al + g);
        }
        if (BTRANS) {
            #pragma unroll
            for (int c = tid; c < 32 * (BN / 8); c += NT) {
                int kr = c / (BN / 8), nc = (c % (BN / 8)) * 8;
                long long g = (long long)(k0 + kr) * ldb + bn + nc;
                uint32_t so = bB + (uint32_t)(kr * LDBT + nc) * 2;
                cp16(aBh + so, Bh + g);
                cp16(aBl + so, Bl + g);
            }
        } else {
            #pragma unroll
            for (int c = tid; c < BN * 4; c += NT) {
                int r = c >> 2, ck = (c & 3) * 8;
                long long g = (long long)(bn + r) * ldb + k0 + ck;
                uint32_t so = bB + (uint32_t)(r * LDA_S + ck) * 2;
                cp16(aBh + so, Bh + g);
                cp16(aBl + so, Bl + g);
            }
        }
        cp_commit();
    };

    const int S = K / 32;
    load_stage(0);

    for (int s = 0; s < S; s++) {
        cp_wait<0>();
        __syncthreads();
        if (s + 1 < S) load_stage(s + 1);

        const int buf = s & 1;
        const uint32_t bA = (uint32_t)buf * SA_E * 2;
        const uint32_t bB = (uint32_t)buf * SB_E * 2;

        #pragma unroll
        for (int kk = 0; kk < 32; kk += 16) {
            uint32_t a_h[4][4], a_l[4][4];
            #pragma unroll
            for (int mi = 0; mi < 4; mi++) {
                uint32_t ao = bA + (uint32_t)((wm + mi * 16 + (lane & 15)) * LDA_S
                                              + kk + (lane >> 4) * 8) * 2;
                ldsm4(a_h[mi], aAh + ao);
                if (TERMS == 3) ldsm4(a_l[mi], aAl + ao);
            }
            uint32_t b_h[4][2], b_l[4][2];
            #pragma unroll
            for (int ni = 0; ni < 2; ni++) {
                uint32_t r4[4];
                if (BTRANS) {
                    uint32_t bo = bB + (uint32_t)((kk + (lane & 15)) * LDBT
                                                  + wn + ni * 16 + (lane >> 4) * 8) * 2;
                    ldsm4t(r4, aBh + bo);
                    b_h[2*ni][0] = r4[0]; b_h[2*ni][1] = r4[1];
                    b_h[2*ni+1][0] = r4[2]; b_h[2*ni+1][1] = r4[3];
                    ldsm4t(r4, aBl + bo);
                    b_l[2*ni][0] = r4[0]; b_l[2*ni][1] = r4[1];
                    b_l[2*ni+1][0] = r4[2]; b_l[2*ni+1][1] = r4[3];
                } else {
                    uint32_t bo = bB + (uint32_t)((wn + ni * 16 + (lane & 15)) * LDA_S
                                                  + kk + (lane >> 4) * 8) * 2;
                    ldsm4(r4, aBh + bo);
                    b_h[2*ni][0] = r4[0]; b_h[2*ni][1] = r4[2];
                    b_h[2*ni+1][0] = r4[1]; b_h[2*ni+1][1] = r4[3];
                    ldsm4(r4, aBl + bo);
                    b_l[2*ni][0] = r4[0]; b_l[2*ni][1] = r4[2];
                    b_l[2*ni+1][0] = r4[1]; b_l[2*ni+1][1] = r4[3];
                }
            }
            #pragma unroll
            for (int mi = 0; mi < 4; mi++)
                #pragma unroll
                for (int ni = 0; ni < 4; ni++) {
                    mma16816(acc[mi][ni], a_h[mi], b_h[ni]);
                    mma16816(acc[mi][ni], a_h[mi], b_l[ni]);
                    if (TERMS == 3) mma16816(acc[mi][ni], a_l[mi], b_h[ni]);
                }
        }
        __syncthreads();
    }

    if (OUT == 0) {
        #pragma unroll
        for (int mi = 0; mi < 4; mi++) {
            const int r0 = bm + wm + mi * 16 + (lane >> 2);
            #pragma unroll
            for (int ni = 0; ni < 4; ni++) {
                const int c = bn + wn + ni * 8 + (lane & 3) * 2;
                *reinterpret_cast<float2*>(&Cf[(long long)r0 * ldc + c]) =
                    make_float2(acc[mi][ni][0] * out_scale, acc[mi][ni][1] * out_scale);
                *reinterpret_cast<float2*>(&Cf[(long long)(r0 + 8) * ldc + c]) =
                    make_float2(acc[mi][ni][2] * out_scale, acc[mi][ni][3] * out_scale);
            }
        }
        return;
    }

    #pragma unroll
    for (int mi = 0; mi < 4; mi++) {
        int r0 = wm + mi * 16 + (lane >> 2);
        #pragma unroll
        for (int ni = 0; ni < 4; ni++) {
            int c = wn + ni * 8 + (lane & 3) * 2;
            sE[r0 * BNP + c]           = acc[mi][ni][0];
            sE[r0 * BNP + c + 1]       = acc[mi][ni][1];
            sE[(r0 + 8) * BNP + c]     = acc[mi][ni][2];
            sE[(r0 + 8) * BNP + c + 1] = acc[mi][ni][3];
        }
    }
    __syncthreads();

    for (int i = tid; i < 128 * BN / 4; i += NT) {
        int r = i / (BN / 4), c = (i % (BN / 4)) * 4;
        float v0 = sE[r * BNP + c]     * out_scale;
        float v1 = sE[r * BNP + c + 1] * out_scale;
        float v2 = sE[r * BNP + c + 2] * out_scale;
        float v3 = sE[r * BNP + c + 3] * out_scale;
        long long go = (long long)(bm + r) * ldc + bn + c;
        if (OUT == 1) {
            *reinterpret_cast<float4*>(&Cf[go]) =
                make_float4(v0 + bias[bn + c], v1 + bias[bn + c + 1],
                            v2 + bias[bn + c + 2], v3 + bias[bn + c + 3]);
        } else if (OUT == 2) {
            f16 h0, l0, h1, l1, h2, l2, h3, l3;
            split_f16(v0, h0, l0); split_f16(v1, h1, l1);
            split_f16(v2, h2, l2); split_f16(v3, h3, l3);
            f162 hh[2] = {__halves2half2(h0, h1), __halves2half2(h2, h3)};
            f162 ll[2] = {__halves2half2(l0, l1), __halves2half2(l2, l3)};
            *reinterpret_cast<float2*>(&Ch[go]) = *reinterpret_cast<float2*>(hh);
            *reinterpret_cast<float2*>(&Cl[go]) = *reinterpret_cast<float2*>(ll);
        } else {
            f162 hh[2] = {__halves2half2(__float2half(v0), __float2half(v1)),
                          __halves2half2(__float2half(v2), __float2half(v3))};
            *reinterpret_cast<float2*>(&Ch[go]) = *reinterpret_cast<float2*>(hh);
        }
    }
}

// ------------- mix v4: 256 threads, 4 adjacent cols/thread ------------------
// Streaming-h pre-mix (4 live inputs), per-gp post-mix (4 live outputs).
// Halves weight-LDS per FMA vs mix2; __launch_bounds__(256,2) -> 2 CTAs/SM.
__global__ void __launch_bounds__(256, 2)
mix_softmax_mix4(const float* __restrict__ dots, f16* __restrict__ ah,
                 const float* __restrict__ pre, const float* __restrict__ post) {
    __shared__ float spre[256], spost[256], sred[16 * 8], sfin[16], sinv[16];
    const int tid = threadIdx.x;
    const int i = blockIdx.x, b = blockIdx.y;
    spre[tid] = pre[tid];
    spost[tid] = post[tid];
    __syncthreads();

    const long long base = (long long)b * HEADS * NSEQ * NSEQ + (long long)i * NSEQ;
    const int j0 = tid * 4;
    const int warp = tid >> 5, lane = tid & 31;

    // ---- pre-mix, streaming over h ----
    float e[16][4] = {};
    #pragma unroll
    for (int h = 0; h < 16; h++) {
        float4 v = *reinterpret_cast<const float4*>(&dots[base + (long long)h * NSEQ * NSEQ + j0]);
        #pragma unroll
        for (int g = 0; g < 16; g++) {
            float w = spre[h * 16 + g];
            e[g][0] += v.x * w; e[g][1] += v.y * w;
            e[g][2] += v.z * w; e[g][3] += v.w * w;
        }
    }

    // ---- block max per g (8 warps) ----
    #pragma unroll
    for (int g = 0; g < 16; g++) {
        float m = fmaxf(fmaxf(e[g][0], e[g][1]), fmaxf(e[g][2], e[g][3]));
        #pragma unroll
        for (int o = 16; o; o >>= 1) m = fmaxf(m, __shfl_xor_sync(0xFFFFFFFFu, m, o));
        if (lane == 0) sred[g * 8 + warp] = m;
    }
    __syncthreads();
    if (tid < 16) {
        float m = -INFINITY;
        #pragma unroll
        for (int w = 0; w < 8; w++) m = fmaxf(m, sred[tid * 8 + w]);
        sfin[tid] = m;
    }
    __syncthreads();

    // ---- exp + block sum per g ----
    #pragma unroll
    for (int g = 0; g < 16; g++) {
        float m = sfin[g];
        e[g][0] = __expf(e[g][0] - m); e[g][1] = __expf(e[g][1] - m);
        e[g][2] = __expf(e[g][2] - m); e[g][3] = __expf(e[g][3] - m);
        float s = (e[g][0] + e[g][1]) + (e[g][2] + e[g][3]);
        #pragma unroll
        for (int o = 16; o; o >>= 1) s += __shfl_xor_sync(0xFFFFFFFFu, s, o);
        if (lane == 0) sred[g * 8 + warp] = s;
    }
    __syncthreads();
    if (tid < 16) {
        float s = 0.f;
        #pragma unroll
        for (int w = 0; w < 8; w++) s += sred[tid * 8 + w];
        sinv[tid] = 1.f / s;
    }
    __syncthreads();

    #pragma unroll
    for (int g = 0; g < 16; g++) {
        float inv = sinv[g];
        e[g][0] *= inv; e[g][1] *= inv; e[g][2] *= inv; e[g][3] *= inv;
    }

    // ---- post-mix, per gp ----
    #pragma unroll
    for (int gp = 0; gp < 16; gp++) {
        float o0 = 0.f, o1 = 0.f, o2 = 0.f, o3 = 0.f;
        #pragma unroll
        for (int g = 0; g < 16; g++) {
            float w = spost[g * 16 + gp];
            o0 += e[g][0] * w; o1 += e[g][1] * w;
            o2 += e[g][2] * w; o3 += e[g][3] * w;
        }
        f162 p[2] = {__halves2half2(__float2half(o0), __float2half(o1)),
                     __halves2half2(__float2half(o2), __float2half(o3))};
        *reinterpret_cast<float2*>(&ah[base + (long long)gp * NSEQ * NSEQ + j0]) =
            *reinterpret_cast<float2*>(p);
    }
}

// ---------------------------------------------------------------------------
static inline int gemm_smem(int BN, bool BT, int terms, bool direct_out) {
    int SA = 128 * 40 * (terms == 3 ? 2 : 1);
    int SB = 2 * (BT ? 32 * (BN + 8) : BN * 40);
    int pipe = 4 * (SA + SB);
    if (direct_out) return pipe;
    int epi = 128 * (BN + 4) * 4;
    return pipe > epi ? pipe : epi;
}

extern "C" void kernel_launch(void* const* d_in, const int* in_sizes, int n_in,
                              void* d_out, int out_size) {
    const float* x        = (const float*)d_in[0];
    const float* Wq       = (const float*)d_in[1];
    const float* Wkv      = (const float*)d_in[2];
    const float* mix_pre  = (const float*)d_in[3];
    const float* mix_post = (const float*)d_in[4];
    const float* Wo       = (const float*)d_in[5];
    const float* bo       = (const float*)d_in[6];
    float* out = (float*)d_out;

    f16 *xh, *xl, *woh, *wol, *kvh, *kvl, *ah, *mh, *qh, *ql;
    float* dots;
    cudaGetSymbolAddress((void**)&xh, g_xh);     cudaGetSymbolAddress((void**)&xl, g_xl);
    cudaGetSymbolAddress((void**)&woh, g_woh);   cudaGetSymbolAddress((void**)&wol, g_wol);
    cudaGetSymbolAddress((void**)&qh, g_qh);     cudaGetSymbolAddress((void**)&ql, g_ql);
    cudaGetSymbolAddress((void**)&kvh, g_kvh);   cudaGetSymbolAddress((void**)&kvl, g_kvl);
    cudaGetSymbolAddress((void**)&ah, g_ah);
    cudaGetSymbolAddress((void**)&mh, g_mh);
    cudaGetSymbolAddress((void**)&dots, g_dots);

    // 0) fused split of all inputs
    split_all<<<(int)((TOT4 + 255) / 256), 256>>>(x, Wq, Wkv, Wo);

    const int SM_PROJ = gemm_smem(128, true, 3, false);
    const int SM_DOTS = gemm_smem(128, false, 3, true);
    const int SM_AV   = gemm_smem(64, true, 2, false);
    const int SM_OUT  = gemm_smem(128, true, 2, false);

    cudaFuncSetAttribute((const void*)mma_gemm<128,8,true,3,2,2,true>,
                         cudaFuncAttributeMaxDynamicSharedMemorySize, SM_PROJ);
    cudaFuncSetAttribute((const void*)mma_gemm<128,8,false,3,0,2,false>,
                         cudaFuncAttributeMaxDynamicSharedMemorySize, SM_DOTS);
    cudaFuncSetAttribute((const void*)mma_gemm<64,4,true,2,3,4,false>,
                         cudaFuncAttributeMaxDynamicSharedMemorySize, SM_AV);
    cudaFuncSetAttribute((const void*)mma_gemm<128,8,true,2,1,2,false>,
                         cudaFuncAttributeMaxDynamicSharedMemorySize, SM_OUT);

    // 1+2) merged projections: bx<8 -> q (SCALE), bx>=8 -> kv   (3-term)
    mma_gemm<128,8,true,3,2,2,true><<<dim3(24, 32, 1), 256, SM_PROJ>>>(
        xh, xl, nullptr, nullptr, nullptr, nullptr, nullptr, nullptr,
        DIM, DIM, 0, 0, 0, 0, 0, 0, 0, 0, 0.f);

    // 3) dots = q @ k^T -> f32 direct stores, z=(b,h)  (3-term)
    mma_gemm<128,8,false,3,0,2,false><<<dim3(8, 8, BATCH * HEADS), 256, SM_DOTS>>>(
        qh, ql, kvh, kvl, dots, nullptr, nullptr, nullptr,
        DHEAD, INNER, 2 * INNER, NSEQ,
        (long long)NSEQ * INNER, DHEAD,
        (long long)NSEQ * 2 * INNER, DHEAD,
        (long long)HEADS * NSEQ * NSEQ, (long long)NSEQ * NSEQ, 1.f);

    // 4) mix_pre -> softmax -> mix_post -> attn hi (fp16)  [v4: 256 thr, 4 cols]
    mix_softmax_mix4<<<dim3(NSEQ, BATCH), 256>>>(dots, ah, mix_pre, mix_post);

    // 5) mid = attn @ v -> hi only, batched z=(b,g)  (2-term, OCC=4)
    mma_gemm<64,4,true,2,3,4,false><<<dim3(1, 8, BATCH * HEADS), 128, SM_AV>>>(
        ah, nullptr, kvh + INNER, kvl + INNER, nullptr, mh, nullptr, nullptr,
        NSEQ, NSEQ, 2 * INNER, INNER,
        (long long)HEADS * NSEQ * NSEQ, (long long)NSEQ * NSEQ,
        (long long)NSEQ * 2 * INNER, DHEAD,
        (long long)NSEQ * INNER, DHEAD, 1.f);

    // 6) out = mid @ Wo + bo -> f32             (2-term)
    mma_gemm<128,8,true,2,1,2,false><<<dim3(8, 32, 1), 256, SM_OUT>>>(
        mh, nullptr, woh, wol, out, nullptr, nullptr, bo,
        INNER, INNER, DIM, DIM, 0, 0, 0, 0, 0, 0, 1.f);
}